// round 9
// baseline (speedup 1.0000x reference)
#include <cuda_runtime.h>
#include <stdint.h>

#define BB 4
#define NN 4096
#define DD 128
#define KK 2048
#define EPSV 1e-10f
#define RPB 8      // rows per gatherg block
#define STG 3      // smem ring stages (dynamic smem)

// ---- scratch (no allocation allowed) ----
__device__ unsigned long long d_keys[BB * NN];   // 128 KB
__device__ int   d_idx[BB * KK];
__device__ float d_vals[BB * KK];

// output layout: g_new | new_h | idx (float32)
#define OFF_G 0
#define OFF_H ((size_t)BB * KK * KK)
#define OFF_I (OFF_H + (size_t)BB * KK * DD)

__device__ __forceinline__ unsigned smem_u32(const void* p) {
    unsigned a;
    asm("{ .reg .u64 t; cvta.to.shared.u64 t, %1; cvt.u32.u64 %0, t; }" : "=r"(a) : "l"(p));
    return a;
}

// ---------------------------------------------------------------------------
// Kernel 1: scores = sigmoid(h . w + b) packed into sortable u64 keys.
// key = (score_bits << 32) | (0xFFFFFFFF - node): descending key order ==
// descending score, ascending node on ties (jax.lax.top_k). 8 nodes/warp.
// ---------------------------------------------------------------------------
__global__ void scores_kernel(const float4* __restrict__ h,
                              const float4* __restrict__ w,
                              const float* __restrict__ bptr) {
    int gwarp = (blockIdx.x * blockDim.x + threadIdx.x) >> 5;
    int lane  = threadIdx.x & 31;
    int n0 = gwarp * 8;
    if (n0 >= BB * NN) return;
    float4 wv = w[lane];
    float4 a[8];
    #pragma unroll
    for (int u = 0; u < 8; u++) a[u] = h[(size_t)(n0 + u) * (DD / 4) + lane];
    float s[8];
    #pragma unroll
    for (int u = 0; u < 8; u++)
        s[u] = a[u].x * wv.x + a[u].y * wv.y + a[u].z * wv.z + a[u].w * wv.w;
    #pragma unroll
    for (int o = 16; o; o >>= 1) {
        #pragma unroll
        for (int u = 0; u < 8; u++) s[u] += __shfl_xor_sync(0xFFFFFFFFu, s[u], o);
    }
    if (lane < 8) {
        int nd = n0 + lane;
        float x  = s[lane] + bptr[0];
        float sc = 1.0f / (1.0f + expf(-x));
        unsigned int sb = __float_as_uint(sc);
        unsigned int node = (unsigned int)(nd & (NN - 1));
        d_keys[nd] = ((unsigned long long)sb << 32) |
                     (unsigned long long)(0xFFFFFFFFu - node);
    }
}

// ---------------------------------------------------------------------------
// Kernel 2: exact rank-by-count (keys unique). 512 threads / 128 nodes per
// block: each node's 4096 compares split across FOUR threads.
// ---------------------------------------------------------------------------
__global__ void __launch_bounds__(512) rank_kernel() {
    __shared__ __align__(16) unsigned long long sk[NN];   // 32 KB
    __shared__ int part[3][128];
    const int b   = blockIdx.x >> 5;
    const int blk = blockIdx.x & 31;
    const int tid = threadIdx.x;
    for (int i = tid; i < NN; i += 512) sk[i] = d_keys[b * NN + i];
    __syncthreads();

    const int node = blk * 128 + (tid & 127);
    const int q    = tid >> 7;
    const unsigned long long my = sk[node];
    const ulonglong2* sk2 = (const ulonglong2*)(sk + q * (NN / 4));
    int r = 0;
    #pragma unroll 8
    for (int i = 0; i < NN / 8; i++) {
        ulonglong2 kk = sk2[i];
        r += (kk.x > my) + (kk.y > my);
    }
    if (q) part[q - 1][tid & 127] = r;
    __syncthreads();
    if (!q) {
        r += part[0][tid] + part[1][tid] + part[2][tid];
        if (r < KK) {
            d_idx [b * KK + r] = node;
            d_vals[b * KK + r] = __uint_as_float((unsigned int)(my >> 32));
        }
    }
}

// ---------------------------------------------------------------------------
// Kernel 3: gathered adjacency + degree normalize, fused new_h + idx.
// 3-stage cp.async ring in DYNAMIC smem (48 KB), lookahead 2: while
// consuming row r, rows r+1 and r+2 are in flight. Next copy issued before
// the current row's output stores.
// ---------------------------------------------------------------------------
__global__ void __launch_bounds__(256) gatherg_kernel(const float* __restrict__ g,
                                                      const float* __restrict__ h,
                                                      float* __restrict__ out) {
    extern __shared__ __align__(16) float buf[];            // [STG][NN], 48 KB
    __shared__ float wsum[8];

    const int b    = blockIdx.y;
    const int base = blockIdx.x * RPB;
    const int tid  = threadIdx.x;
    const unsigned sbase = smem_u32(buf);

    auto issue_row = [&](int r) {
        const int node = d_idx[b * KK + base + r];
        const char* gsrc = (const char*)(g + ((size_t)b * NN + node) * NN) + tid * 16;
        unsigned sdst = sbase + (unsigned)((r % STG) * NN * 4) + tid * 16;
        #pragma unroll
        for (int c = 0; c < 4; c++) {
            asm volatile("cp.async.cg.shared.global [%0], [%1], 16;"
                         :: "r"(sdst + c * 4096), "l"(gsrc + c * 4096) : "memory");
        }
        asm volatile("cp.async.commit_group;" ::: "memory");
    };

    issue_row(0);
    issue_row(1);
    issue_row(2);

    const int4* cp4 = (const int4*)(d_idx + b * KK);
    const int4 c0 = cp4[tid * 2];
    const int4 c1 = cp4[tid * 2 + 1];

    #pragma unroll
    for (int r = 0; r < RPB; r++) {
        const int   row  = b * KK + base + r;
        const int   node = d_idx[row];
        const float v    = d_vals[row];

        // fused new_h + idx (independent of buf; overlaps pending copies)
        if (tid < 32) {
            float4 hv = __ldg((const float4*)(h + ((size_t)b * NN + node) * DD) + tid);
            hv.x *= v; hv.y *= v; hv.z *= v; hv.w *= v;
            ((float4*)(out + OFF_H + (size_t)row * DD))[tid] = hv;
        }
        if (tid == 32) out[OFF_I + row] = (float)node;

        // row r ready when <= min(2, remaining) newer groups still pending
        if (r <= RPB - 3)
            asm volatile("cp.async.wait_group 2;" ::: "memory");
        else if (r == RPB - 2)
            asm volatile("cp.async.wait_group 1;" ::: "memory");
        else
            asm volatile("cp.async.wait_group 0;" ::: "memory");
        __syncthreads();

        const float* srow = buf + (r % STG) * NN;
        float vv[8];
        vv[0] = srow[c0.x]; vv[1] = srow[c0.y]; vv[2] = srow[c0.z]; vv[3] = srow[c0.w];
        vv[4] = srow[c1.x]; vv[5] = srow[c1.y]; vv[6] = srow[c1.z]; vv[7] = srow[c1.w];
        float local = (vv[0] + vv[1]) + (vv[2] + vv[3]) +
                      ((vv[4] + vv[5]) + (vv[6] + vv[7]));
        #pragma unroll
        for (int o = 16; o; o >>= 1) local += __shfl_xor_sync(0xFFFFFFFFu, local, o);
        if ((tid & 31) == 0) wsum[tid >> 5] = local;
        __syncthreads();

        float deg = 0.f;
        #pragma unroll
        for (int wv = 0; wv < 8; wv++) deg += wsum[wv];
        const float inv = 1.0f / (deg + EPSV);

        if (r + 3 < RPB) issue_row(r + 3);   // refill ring before the writes

        float4* dst4 = (float4*)(out + OFF_G + (size_t)row * KK);
        dst4[tid * 2]     = make_float4(vv[0] * inv, vv[1] * inv, vv[2] * inv, vv[3] * inv);
        dst4[tid * 2 + 1] = make_float4(vv[4] * inv, vv[5] * inv, vv[6] * inv, vv[7] * inv);
    }
}

// ---------------------------------------------------------------------------
extern "C" void kernel_launch(void* const* d_in, const int* in_sizes, int n_in,
                              void* d_out, int out_size) {
    const float* g = (const float*)d_in[0];   // [B,N,N]
    const float* h = (const float*)d_in[1];   // [B,N,D]
    const float* w = (const float*)d_in[2];   // [D]
    const float* b = (const float*)d_in[3];   // scalar
    float* out = (float*)d_out;

    const int smem_bytes = STG * NN * 4;      // 48 KB dynamic
    static bool attr_set = false;
    if (!attr_set) {
        cudaFuncSetAttribute(gatherg_kernel,
                             cudaFuncAttributeMaxDynamicSharedMemorySize, smem_bytes);
        attr_set = true;
    }

    scores_kernel<<<(BB * NN) / 32, 128>>>((const float4*)h, (const float4*)w, b);
    rank_kernel<<<BB * 32, 512>>>();
    dim3 grid(KK / RPB, BB);
    gatherg_kernel<<<grid, 256, smem_bytes>>>(g, h, out);
}

// round 10
// speedup vs baseline: 1.1174x; 1.1174x over previous
#include <cuda_runtime.h>
#include <stdint.h>

#define BB 4
#define NN 4096
#define DD 128
#define KK 2048
#define EPSV 1e-10f
#define RPB 4     // rows per gatherg block

// ---- scratch (no allocation allowed) ----
__device__ unsigned long long d_keys[BB * NN];   // 128 KB
__device__ int   d_idx[BB * KK];
__device__ float d_vals[BB * KK];

// output layout: g_new | new_h | idx (float32)
#define OFF_G 0
#define OFF_H ((size_t)BB * KK * KK)
#define OFF_I (OFF_H + (size_t)BB * KK * DD)

__device__ __forceinline__ unsigned smem_u32(const void* p) {
    unsigned a;
    asm("{ .reg .u64 t; cvta.to.shared.u64 t, %1; cvt.u32.u64 %0, t; }" : "=r"(a) : "l"(p));
    return a;
}

// ---------------------------------------------------------------------------
// Kernel 1: scores = sigmoid(h . w + b) packed into sortable u64 keys.
// key = (score_bits << 32) | (0xFFFFFFFF - node): descending key order ==
// descending score, ascending node on ties (jax.lax.top_k). 4 nodes/warp.
// (Exact R7 version — measured best.)
// ---------------------------------------------------------------------------
__global__ void scores_kernel(const float4* __restrict__ h,
                              const float4* __restrict__ w,
                              const float* __restrict__ bptr) {
    int gwarp = (blockIdx.x * blockDim.x + threadIdx.x) >> 5;
    int lane  = threadIdx.x & 31;
    int n0 = gwarp * 4;
    if (n0 >= BB * NN) return;
    float4 wv = w[lane];
    float s[4];
    #pragma unroll
    for (int u = 0; u < 4; u++) {
        float4 a = h[(size_t)(n0 + u) * (DD / 4) + lane];
        s[u] = a.x * wv.x + a.y * wv.y + a.z * wv.z + a.w * wv.w;
    }
    #pragma unroll
    for (int o = 16; o; o >>= 1) {
        #pragma unroll
        for (int u = 0; u < 4; u++) s[u] += __shfl_xor_sync(0xFFFFFFFFu, s[u], o);
    }
    if (lane < 4) {
        int nd = n0 + lane;
        float x  = s[lane] + bptr[0];
        float sc = 1.0f / (1.0f + expf(-x));
        unsigned int sb = __float_as_uint(sc);
        unsigned int node = (unsigned int)(nd & (NN - 1));
        d_keys[nd] = ((unsigned long long)sb << 32) |
                     (unsigned long long)(0xFFFFFFFFu - node);
    }
}

// ---------------------------------------------------------------------------
// Kernel 2: exact rank-by-count (keys unique). 512 threads / 128 nodes per
// block: each node's 4096 compares split across FOUR threads.
// (Exact R7 version — measured best.)
// ---------------------------------------------------------------------------
__global__ void __launch_bounds__(512) rank_kernel() {
    __shared__ __align__(16) unsigned long long sk[NN];   // 32 KB
    __shared__ int part[3][128];
    const int b   = blockIdx.x >> 5;
    const int blk = blockIdx.x & 31;
    const int tid = threadIdx.x;
    for (int i = tid; i < NN; i += 512) sk[i] = d_keys[b * NN + i];
    __syncthreads();

    const int node = blk * 128 + (tid & 127);
    const int q    = tid >> 7;
    const unsigned long long my = sk[node];
    const ulonglong2* sk2 = (const ulonglong2*)(sk + q * (NN / 4));
    int r = 0;
    #pragma unroll 8
    for (int i = 0; i < NN / 8; i++) {
        ulonglong2 kk = sk2[i];
        r += (kk.x > my) + (kk.y > my);
    }
    if (q) part[q - 1][tid & 127] = r;
    __syncthreads();
    if (!q) {
        r += part[0][tid] + part[1][tid] + part[2][tid];
        if (r < KK) {
            d_idx [b * KK + r] = node;
            d_vals[b * KK + r] = __uint_as_float((unsigned int)(my >> 32));
        }
    }
}

// ---------------------------------------------------------------------------
// Kernel 3: gathered adjacency + degree normalize, fused new_h + idx.
// R7 pipeline (2-stage cp.async, lookahead 1, RPB=4) but with 512 threads:
// max thread occupancy (4 blocks x 512 = 2048/SM), 4 columns per thread so
// more warps hide the scattered-LDS latency; one STG.128 per thread per row.
// ---------------------------------------------------------------------------
__global__ void __launch_bounds__(512) gatherg_kernel(const float* __restrict__ g,
                                                      const float* __restrict__ h,
                                                      float* __restrict__ out) {
    __shared__ __align__(16) float buf[2][NN];              // 32 KB
    __shared__ float wsum[16];

    const int b    = blockIdx.y;
    const int base = blockIdx.x * RPB;
    const int tid  = threadIdx.x;

    // one row's 16KB as 2x16B cp.async per thread (512 threads)
    auto issue_row = [&](int r, int st) {
        const int node = d_idx[b * KK + base + r];
        const char* gsrc = (const char*)(g + ((size_t)b * NN + node) * NN) + tid * 16;
        unsigned sdst = smem_u32(buf[st]) + tid * 16;
        #pragma unroll
        for (int c = 0; c < 2; c++) {
            asm volatile("cp.async.cg.shared.global [%0], [%1], 16;"
                         :: "r"(sdst + c * 8192), "l"(gsrc + c * 8192) : "memory");
        }
        asm volatile("cp.async.commit_group;" ::: "memory");
    };

    issue_row(0, 0);
    issue_row(1, 1);

    // column indices: 4 consecutive j per thread, reused for all RPB rows
    const int4 c0 = ((const int4*)(d_idx + b * KK))[tid];

    #pragma unroll
    for (int r = 0; r < RPB; r++) {
        const int   st   = r & 1;
        const int   row  = b * KK + base + r;
        const int   node = d_idx[row];
        const float v    = d_vals[row];

        // fused new_h + idx (independent of buf; overlaps pending copies)
        if (tid < 32) {
            float4 hv = __ldg((const float4*)(h + ((size_t)b * NN + node) * DD) + tid);
            hv.x *= v; hv.y *= v; hv.z *= v; hv.w *= v;
            ((float4*)(out + OFF_H + (size_t)row * DD))[tid] = hv;
        }
        if (tid == 32) out[OFF_I + row] = (float)node;

        if (r < RPB - 1)
            asm volatile("cp.async.wait_group 1;" ::: "memory");
        else
            asm volatile("cp.async.wait_group 0;" ::: "memory");
        __syncthreads();

        const float* srow = buf[st];
        float vv[4];
        vv[0] = srow[c0.x]; vv[1] = srow[c0.y]; vv[2] = srow[c0.z]; vv[3] = srow[c0.w];
        float local = (vv[0] + vv[1]) + (vv[2] + vv[3]);
        #pragma unroll
        for (int o = 16; o; o >>= 1) local += __shfl_xor_sync(0xFFFFFFFFu, local, o);
        if ((tid & 31) == 0) wsum[tid >> 5] = local;
        __syncthreads();

        float deg = 0.f;
        #pragma unroll
        for (int wv = 0; wv < 16; wv++) deg += wsum[wv];
        const float inv = 1.0f / (deg + EPSV);

        if (r + 2 < RPB) issue_row(r + 2, st);   // next fetch before the writes

        float4* dst4 = (float4*)(out + OFF_G + (size_t)row * KK);
        dst4[tid] = make_float4(vv[0] * inv, vv[1] * inv, vv[2] * inv, vv[3] * inv);
    }
}

// ---------------------------------------------------------------------------
extern "C" void kernel_launch(void* const* d_in, const int* in_sizes, int n_in,
                              void* d_out, int out_size) {
    const float* g = (const float*)d_in[0];   // [B,N,N]
    const float* h = (const float*)d_in[1];   // [B,N,D]
    const float* w = (const float*)d_in[2];   // [D]
    const float* b = (const float*)d_in[3];   // scalar
    float* out = (float*)d_out;

    scores_kernel<<<(BB * NN) / 16, 128>>>((const float4*)h, (const float4*)w, b);
    rank_kernel<<<BB * 32, 512>>>();
    dim3 grid(KK / RPB, BB);
    gatherg_kernel<<<grid, 512>>>(g, h, out);
}